// round 16
// baseline (speedup 1.0000x reference)
#include <cuda_runtime.h>
#include <cuda_fp16.h>
#include <math.h>
#include <stdint.h>

#define S_    2048
#define HID_  2048
#define NH_   16
#define NKV_  4
#define D_    128
#define HB_   204
#define RB_   204
#define SCALE_ 0.08838834764831845f
#define L2E_  1.4426950408889634f
#define QKVN_ 3072

// ----------------------------- scratch ---------------------------------
__device__ float g_qkv[S_ * QKVN_];                 // [s][ q(2048) | k(512) | v(512) ]
__device__ __half g_e[(size_t)NH_ * S_ * S_];       // exp(score) fp16; zero above diagonal
__device__ float g_rowsum[NH_ * S_];
__device__ float g_invl1[NH_ * S_], g_invl2[NH_ * S_];
__device__ float g_colsum[NH_ * S_];
__device__ int   g_heavylist[NH_ * HB_];
__device__ uint32_t g_heavybits[NH_ * 64];

__device__ __half g_xh[(size_t)S_ * HID_];                // single fp16 hidden
__device__ __half g_wqkvt[(size_t)QKVN_ * HID_];          // (Wq|Wk|Wv)^T single fp16
__device__ __half g_wot[(size_t)HID_ * HID_];             // Wo^T single fp16
__device__ __half g_qhat[(size_t)NH_ * S_ * D_];          // single fp16 roped Q
__device__ __half g_khat[(size_t)NKV_ * S_ * D_];         // single fp16 roped K
__device__ __half g_vthat[(size_t)NKV_ * D_ * S_];        // single fp16 V^T
__device__ __half g_aohat[(size_t)S_ * HID_];             // single fp16 attention out

// ----------------------------- PTX helpers ------------------------------
__device__ __forceinline__ uint32_t smem_u32(const void* p) {
    uint32_t a;
    asm("{ .reg .u64 t; cvta.to.shared.u64 t, %1; cvt.u32.u64 %0, t; }" : "=r"(a) : "l"(p));
    return a;
}
__device__ __forceinline__ void cp16(uint32_t saddr, const void* gptr) {
    asm volatile("cp.async.cg.shared.global [%0], [%1], 16;" :: "r"(saddr), "l"(gptr));
}
__device__ __forceinline__ void cp_commit() { asm volatile("cp.async.commit_group;"); }
__device__ __forceinline__ void cp_wait0() { asm volatile("cp.async.wait_group 0;" ::: "memory"); }
__device__ __forceinline__ void cp_wait1() { asm volatile("cp.async.wait_group 1;" ::: "memory"); }

__device__ __forceinline__ void ldsm4(uint32_t& r0, uint32_t& r1, uint32_t& r2, uint32_t& r3,
                                      uint32_t addr) {
    asm volatile("ldmatrix.sync.aligned.m8n8.x4.shared.b16 {%0,%1,%2,%3}, [%4];"
                 : "=r"(r0), "=r"(r1), "=r"(r2), "=r"(r3) : "r"(addr));
}
__device__ __forceinline__ void mma16816(float* d, const uint32_t* a, const uint32_t* b) {
    asm volatile(
        "mma.sync.aligned.m16n8k16.row.col.f32.f16.f16.f32 "
        "{%0,%1,%2,%3}, {%4,%5,%6,%7}, {%8,%9}, {%0,%1,%2,%3};"
        : "+f"(d[0]), "+f"(d[1]), "+f"(d[2]), "+f"(d[3])
        : "r"(a[0]), "r"(a[1]), "r"(a[2]), "r"(a[3]), "r"(b[0]), "r"(b[1]));
}
__device__ __forceinline__ float fexp(float x) {   // e^x via MUFU
    float y;
    asm("ex2.approx.ftz.f32 %0, %1;" : "=f"(y) : "f"(x * L2E_));
    return y;
}
__device__ __forceinline__ float fexp2p3(float x) { // 2^x via FMA pipe, deg-3
    float n = rintf(x);
    float f = x - n;
    float p = 5.5490603e-2f;
    p = fmaf(p, f, 2.4022651e-1f);
    p = fmaf(p, f, 6.9315308e-1f);
    p = fmaf(p, f, 9.9999989e-1f);
    return p * __int_as_float(((int)n + 127) << 23);
}
__device__ __forceinline__ uint32_t packh(float p0, float p1) {
    __half2 h = __floats2half2_rn(p0, p1);
    return *(uint32_t*)&h;
}

// ------------------------- tile loaders -------------------------
__device__ __forceinline__ void load_tile_async(uint32_t sbase, const __half* src,
                                                int ld, int row0, int kbase, int tid) {
#pragma unroll
    for (int t = 0; t < 4; t++) {       // 128 rows x 128 B
        int u = tid + t * 256;
        int row = u >> 3, seg = u & 7;
        uint32_t bo = (uint32_t)(row * 128 + seg * 16);
        bo ^= (bo >> 3) & 0x70;
        cp16(sbase + bo, src + (size_t)(row0 + row) * ld + kbase + seg * 8);
    }
}
__device__ __forceinline__ void load_tile64_async(uint32_t sbase, const __half* src,
                                                  int ld, int row0, int kbase, int tid) {
#pragma unroll
    for (int t = 0; t < 2; t++) {       // 64 rows x 128 B
        int u = tid + t * 256;
        int row = u >> 3, seg = u & 7;
        uint32_t bo = (uint32_t)(row * 128 + seg * 16);
        bo ^= (bo >> 3) & 0x70;
        cp16(sbase + bo, src + (size_t)(row0 + row) * ld + kbase + seg * 8);
    }
}

// ------------------------- 128x128 HMMA GEMM -------------------------
// mode 0: plain fp32 store to C.
// mode 2: Eh = fp16(exp(scale*s)) for j<=i (0 above), hybrid exp, fused row sums.
__global__ __launch_bounds__(256, 2) void mma_gemm(
    const __half* __restrict__ A, size_t aStrideZ, int aLd,
    const __half* __restrict__ Bt, size_t bStrideZ, int bShift, int bLd,
    float* __restrict__ C, __half* __restrict__ Eh, size_t cStrideZ, int ldc,
    int Kp, int mode, float* __restrict__ rowsum) {
    int z = blockIdx.z;
    int i0 = blockIdx.y * 128, j0 = blockIdx.x * 128;
    if (mode == 2 && j0 > i0 + 127) return;

    const __half* Az = A + (size_t)z * aStrideZ;
    const __half* Bz = Bt + (size_t)(z >> bShift) * bStrideZ;
    int tid = threadIdx.x, wid = tid >> 5;
    uint32_t lane = tid & 31;

    extern __shared__ char dsm[];
    char* tile = (char*)(((uintptr_t)dsm + 1023) & ~(uintptr_t)1023);
    uint32_t sA[2] = { smem_u32(tile), smem_u32(tile) + 16384 };
    uint32_t sB[2] = { smem_u32(tile) + 32768, smem_u32(tile) + 49152 };

    int warp_m = wid >> 2;
    int warp_n = wid & 3;

    float acc[4][4][4];
#pragma unroll
    for (int i = 0; i < 4; i++)
#pragma unroll
        for (int j = 0; j < 4; j++)
#pragma unroll
            for (int r = 0; r < 4; r++) acc[i][j][r] = 0.f;

    load_tile_async(sA[0], Az, aLd, i0, 0, tid);
    load_tile_async(sB[0], Bz, bLd, j0, 0, tid);
    cp_commit();

    const int NC = Kp >> 6;
    for (int c = 0; c < NC; c++) {
        if (c + 1 < NC) {
            load_tile_async(sA[(c + 1) & 1], Az, aLd, i0, (c + 1) * 64, tid);
            load_tile_async(sB[(c + 1) & 1], Bz, bLd, j0, (c + 1) * 64, tid);
            cp_commit();
            cp_wait1();
        } else {
            cp_wait0();
        }
        __syncthreads();

        uint32_t a_base = sA[c & 1], b_base = sB[c & 1];
#pragma unroll
        for (int ks = 0; ks < 4; ks++) {
            uint32_t a[4][4], b[2][4];
#pragma unroll
            for (int mf = 0; mf < 4; mf++) {
                int row = 64 * warp_m + 16 * mf + (lane & 7) + (((lane >> 3) & 1) << 3);
                int colb = (16 * ks + (((lane >> 4) & 1) << 3)) * 2;
                uint32_t off = (uint32_t)(row * 128 + colb);
                off ^= (off >> 3) & 0x70;
                ldsm4(a[mf][0], a[mf][1], a[mf][2], a[mf][3], a_base + off);
            }
#pragma unroll
            for (int nf2 = 0; nf2 < 2; nf2++) {
                int row = 32 * warp_n + 16 * nf2 + (lane & 7) + (((lane >> 4) & 1) << 3);
                int colb = (16 * ks + (((lane >> 3) & 1) << 3)) * 2;
                uint32_t off = (uint32_t)(row * 128 + colb);
                off ^= (off >> 3) & 0x70;
                ldsm4(b[nf2][0], b[nf2][1], b[nf2][2], b[nf2][3], b_base + off);
            }
#pragma unroll
            for (int mf = 0; mf < 4; mf++)
#pragma unroll
                for (int nf = 0; nf < 4; nf++)
                    mma16816(acc[mf][nf], a[mf], &b[nf >> 1][(nf & 1) * 2]);
        }
        __syncthreads();
    }

    if (mode == 0) {
        float* Cz = C + (size_t)z * cStrideZ;
#pragma unroll
        for (int mf = 0; mf < 4; mf++) {
            int r0 = i0 + 64 * warp_m + 16 * mf + (int)(lane >> 2);
#pragma unroll
            for (int nf = 0; nf < 4; nf++) {
                int c0 = j0 + 32 * warp_n + 8 * nf + (int)(lane & 3) * 2;
                *(float2*)(Cz + (size_t)r0 * ldc + c0) = make_float2(acc[mf][nf][0], acc[mf][nf][1]);
                *(float2*)(Cz + (size_t)(r0 + 8) * ldc + c0) = make_float2(acc[mf][nf][2], acc[mf][nf][3]);
            }
        }
        return;
    }

    // mode 2: exp epilogue (10/16 MUFU + 6/16 deg-3 poly), fp16 store, fused row sums
    __half* Ez = Eh + (size_t)z * cStrideZ;
    const float cl = SCALE_ * L2E_;
    float rs0[4], rs1[4];
#pragma unroll
    for (int mf = 0; mf < 4; mf++) {
        int r0 = i0 + 64 * warp_m + 16 * mf + (int)(lane >> 2);
        float s0 = 0.f, s1 = 0.f;
#pragma unroll
        for (int nf = 0; nf < 4; nf++) {
            int c0 = j0 + 32 * warp_n + 8 * nf + (int)(lane & 3) * 2;
            float d0 = acc[mf][nf][0], d1 = acc[mf][nf][1];
            float d2 = acc[mf][nf][2], d3 = acc[mf][nf][3];
            if (nf < 2) {
                d0 = (c0     <= r0)     ? fexp(d0 * SCALE_) : 0.f;
                d1 = (c0 + 1 <= r0)     ? fexp(d1 * SCALE_) : 0.f;
                d2 = (c0     <= r0 + 8) ? fexp(d2 * SCALE_) : 0.f;
                d3 = (c0 + 1 <= r0 + 8) ? fexp(d3 * SCALE_) : 0.f;
            } else if (nf == 2) {
                d0 = (c0     <= r0)     ? fexp(d0 * SCALE_) : 0.f;
                d1 = (c0 + 1 <= r0)     ? fexp(d1 * SCALE_) : 0.f;
                d2 = (c0     <= r0 + 8) ? fexp2p3(d2 * cl) : 0.f;
                d3 = (c0 + 1 <= r0 + 8) ? fexp2p3(d3 * cl) : 0.f;
            } else {
                d0 = (c0     <= r0)     ? fexp2p3(d0 * cl) : 0.f;
                d1 = (c0 + 1 <= r0)     ? fexp2p3(d1 * cl) : 0.f;
                d2 = (c0     <= r0 + 8) ? fexp2p3(d2 * cl) : 0.f;
                d3 = (c0 + 1 <= r0 + 8) ? fexp2p3(d3 * cl) : 0.f;
            }
            __half2 h01 = __floats2half2_rn(d0, d1);
            __half2 h23 = __floats2half2_rn(d2, d3);
            *(uint32_t*)(Ez + (size_t)r0 * ldc + c0) = *(uint32_t*)&h01;
            *(uint32_t*)(Ez + (size_t)(r0 + 8) * ldc + c0) = *(uint32_t*)&h23;
            float2 f01 = __half22float2(h01);
            float2 f23 = __half22float2(h23);
            s0 += f01.x + f01.y;
            s1 += f23.x + f23.y;
        }
        rs0[mf] = s0; rs1[mf] = s1;
    }
    {
        float* rz = rowsum + (size_t)z * S_;
#pragma unroll
        for (int mf = 0; mf < 4; mf++) {
            float v0 = rs0[mf], v1 = rs1[mf];
            v0 += __shfl_xor_sync(0xFFFFFFFF, v0, 1);
            v0 += __shfl_xor_sync(0xFFFFFFFF, v0, 2);
            v1 += __shfl_xor_sync(0xFFFFFFFF, v1, 1);
            v1 += __shfl_xor_sync(0xFFFFFFFF, v1, 2);
            if ((lane & 3) == 0) {
                int r0 = i0 + 64 * warp_m + 16 * mf + (int)(lane >> 2);
                atomicAdd(rz + r0, v0);
                atomicAdd(rz + r0 + 8, v1);
            }
        }
    }
}

// ------------------- 64x128 HMMA GEMM (3 CTAs/SM; for QKV) ----------------
__global__ __launch_bounds__(256, 3) void mma_gemm64(
    const __half* __restrict__ A, int aLd,
    const __half* __restrict__ Bt, int bLd,
    float* __restrict__ C, int ldc, int Kp) {
    int i0 = blockIdx.y * 64, j0 = blockIdx.x * 128;
    int tid = threadIdx.x, wid = tid >> 5;
    uint32_t lane = tid & 31;

    extern __shared__ char dsm[];
    char* tile = (char*)(((uintptr_t)dsm + 1023) & ~(uintptr_t)1023);
    uint32_t sA[2] = { smem_u32(tile), smem_u32(tile) + 8192 };
    uint32_t sB[2] = { smem_u32(tile) + 16384, smem_u32(tile) + 32768 };

    int warp_m = wid >> 2;   // 0..1 -> 32-row slabs
    int warp_n = wid & 3;    // 0..3 -> 32-col slabs

    float acc[2][4][4];
#pragma unroll
    for (int i = 0; i < 2; i++)
#pragma unroll
        for (int j = 0; j < 4; j++)
#pragma unroll
            for (int r = 0; r < 4; r++) acc[i][j][r] = 0.f;

    load_tile64_async(sA[0], A, aLd, i0, 0, tid);
    load_tile_async(sB[0], Bt, bLd, j0, 0, tid);
    cp_commit();

    const int NC = Kp >> 6;
    for (int c = 0; c < NC; c++) {
        if (c + 1 < NC) {
            load_tile64_async(sA[(c + 1) & 1], A, aLd, i0, (c + 1) * 64, tid);
            load_tile_async(sB[(c + 1) & 1], Bt, bLd, j0, (c + 1) * 64, tid);
            cp_commit();
            cp_wait1();
        } else {
            cp_wait0();
        }
        __syncthreads();

        uint32_t a_base = sA[c & 1], b_base = sB[c & 1];
#pragma unroll
        for (int ks = 0; ks < 4; ks++) {
            uint32_t a[2][4], b[2][4];
#pragma unroll
            for (int mf = 0; mf < 2; mf++) {
                int row = 32 * warp_m + 16 * mf + (lane & 7) + (((lane >> 3) & 1) << 3);
                int colb = (16 * ks + (((lane >> 4) & 1) << 3)) * 2;
                uint32_t off = (uint32_t)(row * 128 + colb);
                off ^= (off >> 3) & 0x70;
                ldsm4(a[mf][0], a[mf][1], a[mf][2], a[mf][3], a_base + off);
            }
#pragma unroll
            for (int nf2 = 0; nf2 < 2; nf2++) {
                int row = 32 * warp_n + 16 * nf2 + (lane & 7) + (((lane >> 4) & 1) << 3);
                int colb = (16 * ks + (((lane >> 3) & 1) << 3)) * 2;
                uint32_t off = (uint32_t)(row * 128 + colb);
                off ^= (off >> 3) & 0x70;
                ldsm4(b[nf2][0], b[nf2][1], b[nf2][2], b[nf2][3], b_base + off);
            }
#pragma unroll
            for (int mf = 0; mf < 2; mf++)
#pragma unroll
                for (int nf = 0; nf < 4; nf++)
                    mma16816(acc[mf][nf], a[mf], &b[nf >> 1][(nf & 1) * 2]);
        }
        __syncthreads();
    }

#pragma unroll
    for (int mf = 0; mf < 2; mf++) {
        int r0 = i0 + 32 * warp_m + 16 * mf + (int)(lane >> 2);
#pragma unroll
        for (int nf = 0; nf < 4; nf++) {
            int c0 = j0 + 32 * warp_n + 8 * nf + (int)(lane & 3) * 2;
            *(float2*)(C + (size_t)r0 * ldc + c0) = make_float2(acc[mf][nf][0], acc[mf][nf][1]);
            *(float2*)(C + (size_t)(r0 + 8) * ldc + c0) = make_float2(acc[mf][nf][2], acc[mf][nf][3]);
        }
    }
}

// ------------------ fused PV (masked P on the fly, single-pass fp16) --------------
__global__ __launch_bounds__(256, 2) void pv_mma(
    const __half* __restrict__ vthat,
    const __half* __restrict__ e, const float* __restrict__ invl2,
    const uint32_t* __restrict__ heavybits,
    __half* __restrict__ aohat) {
    int i0 = (int)(gridDim.x - 1 - blockIdx.x) * 128;   // heavy blocks first
    int h = blockIdx.y, kh = h >> 2;
    int tid = threadIdx.x, wid = tid >> 5;
    uint32_t lane = tid & 31;
    int warp_m = wid >> 2, warp_n = wid & 3;

    extern __shared__ char dsm[];
    char* tile = (char*)(((uintptr_t)dsm + 1023) & ~(uintptr_t)1023);
    char* pP = tile;
    uint32_t sP = smem_u32(pP);
    uint32_t sV[2] = { smem_u32(tile) + 16384, smem_u32(tile) + 32768 };

    __shared__ uint32_t sbits[64];
    if (tid < 64) sbits[tid] = heavybits[h * 64 + tid];

    int r = tid >> 1, half = tid & 1;
    int gi = i0 + r;
    float il = invl2[h * S_ + gi];
    const __half* erow = e + ((size_t)h * S_ + gi) * S_ + half * 32;
    const __half* Vz = vthat + (size_t)kh * D_ * S_;

    float acc[4][4][4];
#pragma unroll
    for (int i = 0; i < 4; i++)
#pragma unroll
        for (int j = 0; j < 4; j++)
#pragma unroll
            for (int q = 0; q < 4; q++) acc[i][j][q] = 0.f;

    const int NCH = (i0 >> 6) + 2;
    load_tile_async(sV[0], Vz, S_, 0, 0, tid);
    cp_commit();
    __syncthreads();

    for (int c = 0; c < NCH; c++) {
        int j0 = c * 64;
        bool pre = (c + 1 < NCH);
        if (pre) {
            load_tile_async(sV[(c + 1) & 1], Vz, S_, 0, (c + 1) * 64, tid);
            cp_commit();
        }
        uint32_t hib[16];
        const __half* ep = erow + j0;
        int gjb = j0 + half * 32;
#pragma unroll
        for (int w = 0; w < 4; w++) {
            uint4 ev = *(const uint4*)(ep + w * 8);
            float2 f0 = __half22float2(*(__half2*)&ev.x);
            float2 f1 = __half22float2(*(__half2*)&ev.y);
            float2 f2 = __half22float2(*(__half2*)&ev.z);
            float2 f3 = __half22float2(*(__half2*)&ev.w);
            float pv[8] = { f0.x, f0.y, f1.x, f1.y, f2.x, f2.y, f3.x, f3.y };
#pragma unroll
            for (int u = 0; u < 8; u++) {
                int gj = gjb + w * 8 + u;
                bool keep = (gj <= gi) &&
                            ((gi - gj <= RB_) || ((sbits[gj >> 5] >> (gj & 31)) & 1u));
                pv[u] = keep ? pv[u] * il : 0.f;
            }
            hib[w * 4 + 0] = packh(pv[0], pv[1]);
            hib[w * 4 + 1] = packh(pv[2], pv[3]);
            hib[w * 4 + 2] = packh(pv[4], pv[5]);
            hib[w * 4 + 3] = packh(pv[6], pv[7]);
        }
#pragma unroll
        for (int sg = 0; sg < 4; sg++) {
            uint32_t bo = (uint32_t)(r * 128 + half * 64 + sg * 16);
            bo ^= (bo >> 3) & 0x70;
            *(uint4*)(pP + bo) = make_uint4(hib[sg * 4], hib[sg * 4 + 1], hib[sg * 4 + 2], hib[sg * 4 + 3]);
        }
        if (pre) cp_wait1(); else cp_wait0();
        __syncthreads();

        uint32_t b_base = sV[c & 1];
#pragma unroll
        for (int ks = 0; ks < 4; ks++) {
            uint32_t a[4][4], b[2][4];
#pragma unroll
            for (int mf = 0; mf < 4; mf++) {
                int row = 64 * warp_m + 16 * mf + (lane & 7) + (((lane >> 3) & 1) << 3);
                int colb = (16 * ks + (((lane >> 4) & 1) << 3)) * 2;
                uint32_t off = (uint32_t)(row * 128 + colb);
                off ^= (off >> 3) & 0x70;
                ldsm4(a[mf][0], a[mf][1], a[mf][2], a[mf][3], sP + off);
            }
#pragma unroll
            for (int nf2 = 0; nf2 < 2; nf2++) {
                int row = 32 * warp_n + 16 * nf2 + (lane & 7) + (((lane >> 4) & 1) << 3);
                int colb = (16 * ks + (((lane >> 3) & 1) << 3)) * 2;
                uint32_t off = (uint32_t)(row * 128 + colb);
                off ^= (off >> 3) & 0x70;
                ldsm4(b[nf2][0], b[nf2][1], b[nf2][2], b[nf2][3], b_base + off);
            }
#pragma unroll
            for (int mf = 0; mf < 4; mf++)
#pragma unroll
                for (int nf = 0; nf < 4; nf++)
                    mma16816(acc[mf][nf], a[mf], &b[nf >> 1][(nf & 1) * 2]);
        }
        __syncthreads();
    }

#pragma unroll
    for (int mf = 0; mf < 4; mf++) {
        int r0 = i0 + 64 * warp_m + 16 * mf + (int)(lane >> 2);
#pragma unroll
        for (int nf = 0; nf < 4; nf++) {
            int c0 = 32 * warp_n + 8 * nf + (int)(lane & 3) * 2;
#pragma unroll
            for (int rr = 0; rr < 2; rr++) {
                uint32_t hi = packh(acc[mf][nf][rr * 2], acc[mf][nf][rr * 2 + 1]);
                size_t b0 = (size_t)(r0 + rr * 8) * HID_ + h * D_ + c0;
                *(uint32_t*)(aohat + b0) = hi;
            }
        }
    }
}

// ----------------------- conversion kernels -------------------
__global__ void tofp16_kernel(const float* __restrict__ A, __half* __restrict__ out, int n) {
    int idx = blockIdx.x * blockDim.x + threadIdx.x;
    if (idx < n) out[idx] = __float2half_rn(A[idx]);
}

__global__ void heads_single(const float* __restrict__ src, int ld,
                             __half* __restrict__ out, int nh) {
    int idx = blockIdx.x * blockDim.x + threadIdx.x;
    if (idx >= S_ * nh * D_) return;
    int d = idx & 127;
    int h = (idx >> 7) % nh;
    int s = idx / (nh * D_);
    float x = src[(size_t)s * ld + h * D_ + d];
    out[((size_t)h * S_ + s) * D_ + d] = __float2half_rn(x);
}

__global__ void transpose_half(const float* __restrict__ src, int ldsrc, int K, int Nper,
                               __half* __restrict__ out) {
    int z = blockIdx.z;
    const float* s = src + (size_t)z * Nper;
    __half* o = out + (size_t)z * Nper * K;
    __shared__ float t[32][33];
    int k0 = blockIdx.y * 32, n0 = blockIdx.x * 32;
    int tx = threadIdx.x, ty = threadIdx.y;
#pragma unroll
    for (int r = 0; r < 4; r++) {
        int k = k0 + ty + 8 * r;
        t[ty + 8 * r][tx] = s[(size_t)k * ldsrc + n0 + tx];
    }
    __syncthreads();
#pragma unroll
    for (int r = 0; r < 4; r++) {
        int n = n0 + ty + 8 * r, k = k0 + tx;
        o[(size_t)n * K + k] = __float2half_rn(t[tx][ty + 8 * r]);
    }
}

// --------------------------------- RoPE ---------------------------------
__global__ void rope_kernel(float* x, int nh, int ld) {
    int idx = blockIdx.x * blockDim.x + threadIdx.x;
    if (idx >= S_ * nh * 64) return;
    int d = idx & 63;
    int rest = idx >> 6;
    int h = rest % nh;
    int s = rest / nh;
    float* base = x + (size_t)s * ld + h * 128;
    float x1 = base[d], x2 = base[d + 64];
    float inv = powf(10000.f, -(float)d * (1.f / 64.f));
    float ang = (float)s * inv;
    float c, sn;
    sincosf(ang, &sn, &c);
    base[d] = x1 * c - x2 * sn;
    base[d + 64] = x2 * c + x1 * sn;
}

// ------------------ invl1 = 1 / rowsum -----------------------------------
__global__ void invl_kernel(const float* __restrict__ rs, float* __restrict__ il) {
    int i = blockIdx.x * 256 + threadIdx.x;
    il[i] = 1.f / rs[i];
}

// coalesced column sums over fp16 e (rows above diagonal are exactly zero)
__global__ __launch_bounds__(256) void colsum_kernel() {
    int h = blockIdx.y;
    int j0 = blockIdx.x * 256;
    int j = j0 + threadIdx.x;
    const __half* base = g_e + (size_t)h * S_ * S_;
    __shared__ float il[S_];
    for (int i = j0 + threadIdx.x; i < S_; i += 256)
        il[i] = g_invl1[h * S_ + i];
    __syncthreads();
    float a0 = 0.f, a1 = 0.f, a2 = 0.f, a3 = 0.f;
    for (int i = j0; i < S_; i += 4) {
        a0 += __half2float(base[(size_t)(i    ) * S_ + j]) * il[i];
        a1 += __half2float(base[(size_t)(i + 1) * S_ + j]) * il[i + 1];
        a2 += __half2float(base[(size_t)(i + 2) * S_ + j]) * il[i + 2];
        a3 += __half2float(base[(size_t)(i + 3) * S_ + j]) * il[i + 3];
    }
    g_colsum[h * S_ + j] = (a0 + a1) + (a2 + a3);
}

__global__ __launch_bounds__(256) void topk_kernel() {
    int h = blockIdx.x;
    int tid = threadIdx.x;
    int lane = tid & 31, w = tid >> 5;
    __shared__ float vals[S_];
    __shared__ float wbv[8];
    __shared__ int wbi[8];
    __shared__ uint32_t bits[64];
    for (int j = tid; j < S_; j += 256) vals[j] = g_colsum[h * S_ + j];
    if (tid < 64) bits[tid] = 0;
    __syncthreads();
    for (int it = 0; it < HB_; it++) {
        float best = -INFINITY; int besti = 1 << 30;
        for (int j = tid; j < S_; j += 256) {
            float v = vals[j];
            if (v > best || (v == best && j < besti)) { best = v; besti = j; }
        }
#pragma unroll
        for (int off = 16; off > 0; off >>= 1) {
            float ov = __shfl_xor_sync(0xFFFFFFFF, best, off);
            int oi = __shfl_xor_sync(0xFFFFFFFF, besti, off);
            if (ov > best || (ov == best && oi < besti)) { best = ov; besti = oi; }
        }
        if (lane == 0) { wbv[w] = best; wbi[w] = besti; }
        __syncthreads();
        if (tid == 0) {
            float b = wbv[0]; int bi2 = wbi[0];
#pragma unroll
            for (int q = 1; q < 8; q++)
                if (wbv[q] > b || (wbv[q] == b && wbi[q] < bi2)) { b = wbv[q]; bi2 = wbi[q]; }
            g_heavylist[h * HB_ + it] = bi2;
            bits[bi2 >> 5] |= (1u << (bi2 & 31));
            vals[bi2] = -INFINITY;
        }
        __syncthreads();
    }
    if (tid < 64) g_heavybits[h * 64 + tid] = bits[tid];
}

// ------ pass-2: invl2 = 1/sum(e over band + heavy) ------
__global__ __launch_bounds__(256) void rowsum2_kernel() {
    int h = blockIdx.y;
    int tid = threadIdx.x;
    __shared__ int hl[HB_];
    for (int t = tid; t < HB_; t += 256) hl[t] = g_heavylist[h * HB_ + t];
    __syncthreads();

    int w = tid >> 5, lane = tid & 31;
    int i = blockIdx.x * 8 + w;
    const __half* erow = g_e + (size_t)(h * S_ + i) * S_;
    int lo = i - RB_; if (lo < 0) lo = 0;

    float l = 0.f;
    for (int j = lo + lane; j <= i; j += 32) l += __half2float(erow[j]);
    for (int t = lane; t < HB_; t += 32) {
        int j = hl[t];
        if (j < lo) l += __half2float(erow[j]);
    }
#pragma unroll
    for (int off = 16; off > 0; off >>= 1)
        l += __shfl_xor_sync(0xFFFFFFFF, l, off);
    if (lane == 0) g_invl2[h * S_ + i] = 1.f / l;
}

// ------------------------------ launcher ---------------------------------
extern "C" void kernel_launch(void* const* d_in, const int* in_sizes, int n_in,
                              void* d_out, int out_size) {
    const float* hidden = (const float*)d_in[0];
    const float* Wq = (const float*)d_in[1];
    const float* Wk = (const float*)d_in[2];
    const float* Wv = (const float*)d_in[3];
    const float* Wo = (const float*)d_in[4];
    float* out = (float*)d_out;

    float *qkv, *rsum, *il1, *il2;
    __half* e;
    uint32_t* hbits;
    __half *xh, *wqkvt, *wot, *qhat, *khat, *vthat, *aohat;
    cudaGetSymbolAddress((void**)&qkv, g_qkv);
    cudaGetSymbolAddress((void**)&e, g_e);
    cudaGetSymbolAddress((void**)&rsum, g_rowsum);
    cudaGetSymbolAddress((void**)&il1, g_invl1);
    cudaGetSymbolAddress((void**)&il2, g_invl2);
    cudaGetSymbolAddress((void**)&hbits, g_heavybits);
    cudaGetSymbolAddress((void**)&xh, g_xh);
    cudaGetSymbolAddress((void**)&wqkvt, g_wqkvt);
    cudaGetSymbolAddress((void**)&wot, g_wot);
    cudaGetSymbolAddress((void**)&qhat, g_qhat);
    cudaGetSymbolAddress((void**)&khat, g_khat);
    cudaGetSymbolAddress((void**)&vthat, g_vthat);
    cudaGetSymbolAddress((void**)&aohat, g_aohat);

    const int SMEM_GEMM = 66560;
    const int SMEM_G64 = 50176;
    const int SMEM_PV = 50176;
    cudaFuncSetAttribute(mma_gemm, cudaFuncAttributeMaxDynamicSharedMemorySize, SMEM_GEMM);
    cudaFuncSetAttribute(mma_gemm64, cudaFuncAttributeMaxDynamicSharedMemorySize, SMEM_G64);
    cudaFuncSetAttribute(pv_mma, cudaFuncAttributeMaxDynamicSharedMemorySize, SMEM_PV);

    // conversions (QKV mma is launch #6 -> ncu -s 5 capture)
    tofp16_kernel<<<(S_ * HID_ + 255) / 256, 256>>>(hidden, xh, S_ * HID_);
    transpose_half<<<dim3(HID_ / 32, HID_ / 32, 1), dim3(32, 8)>>>(Wq, HID_, HID_, HID_, wqkvt);
    transpose_half<<<dim3((NKV_ * D_) / 32, HID_ / 32, 1), dim3(32, 8)>>>(
        Wk, NKV_ * D_, HID_, NKV_ * D_, wqkvt + (size_t)HID_ * HID_);
    transpose_half<<<dim3((NKV_ * D_) / 32, HID_ / 32, 1), dim3(32, 8)>>>(
        Wv, NKV_ * D_, HID_, NKV_ * D_, wqkvt + (size_t)(HID_ + NKV_ * D_) * HID_);
    transpose_half<<<dim3(HID_ / 32, HID_ / 32, 1), dim3(32, 8)>>>(Wo, HID_, HID_, HID_, wot);

    // 6. fused QKV projection (64-row tiles, 3 CTAs/SM: 24x32 grid)
    mma_gemm64<<<dim3(QKVN_ / 128, S_ / 64), 256, SMEM_G64>>>(
        xh, HID_, wqkvt, HID_, qkv, QKVN_, HID_);

    // RoPE (in place inside g_qkv)
    rope_kernel<<<(S_ * NH_ * 64 + 255) / 256, 256>>>(qkv, NH_, QKVN_);
    rope_kernel<<<(S_ * NKV_ * 64 + 255) / 256, 256>>>(qkv + HID_, NKV_, QKVN_);

    // roped Q/K -> single fp16 per-head; V -> single fp16 V^T
    heads_single<<<(S_ * NH_ * D_ + 255) / 256, 256>>>(qkv, QKVN_, qhat, NH_);
    heads_single<<<(S_ * NKV_ * D_ + 255) / 256, 256>>>(qkv + HID_, QKVN_, khat, NKV_);
    transpose_half<<<dim3(D_ / 32, S_ / 32, NKV_), dim3(32, 8)>>>(
        qkv + HID_ + NKV_ * D_, QKVN_, S_, D_, vthat);

    // zero rowsum accumulator
    cudaMemsetAsync(rsum, 0, NH_ * S_ * sizeof(float));

    // e = fp16(exp(scale * QK^T)), single fp16 both sides, Kp = D
    mma_gemm<<<dim3(S_ / 128, S_ / 128, NH_), 256, SMEM_GEMM>>>(
        qhat, (size_t)S_ * D_, D_, khat, (size_t)S_ * D_, 2, D_,
        nullptr, e, (size_t)S_ * S_, S_, D_, 2, rsum);

    // H2O: invl1, colsum, topk
    invl_kernel<<<NH_ * S_ / 256, 256>>>(rsum, il1);
    colsum_kernel<<<dim3(S_ / 256, NH_), 256>>>();
    topk_kernel<<<NH_, 256>>>();

    // invl2
    rowsum2_kernel<<<dim3(S_ / 8, NH_), 256>>>();

    // fused masked PV -> aohat (single fp16)
    pv_mma<<<dim3(S_ / 128, NH_), 256, SMEM_PV>>>(vthat, e, il2, hbits, aohat);

    // output projection (128-tile kernel: 256 blocks fit one wave)
    mma_gemm<<<dim3(HID_ / 128, S_ / 128, 1), 256, SMEM_GEMM>>>(
        aohat, 0, HID_, wot, 0, 0, HID_,
        out, nullptr, 0, HID_, HID_, 0, nullptr);
}

// round 17
// speedup vs baseline: 1.0432x; 1.0432x over previous
#include <cuda_runtime.h>
#include <cuda_fp16.h>
#include <math.h>
#include <stdint.h>

#define S_    2048
#define HID_  2048
#define NH_   16
#define NKV_  4
#define D_    128
#define HB_   204
#define RB_   204
#define SCALE_ 0.08838834764831845f
#define L2E_  1.4426950408889634f
#define QKVN_ 3072

// ----------------------------- scratch ---------------------------------
__device__ float g_qkv[S_ * QKVN_];                 // [s][ q(2048) | k(512) | v(512) ]
__device__ __half g_e[(size_t)NH_ * S_ * S_];       // exp(score) fp16; zero above diagonal
__device__ float g_rowsum[NH_ * S_];
__device__ float g_invl1[NH_ * S_], g_invl2[NH_ * S_];
__device__ float g_colsum[NH_ * S_];
__device__ int   g_heavylist[NH_ * HB_];
__device__ uint32_t g_heavybits[NH_ * 64];

__device__ __half g_xh[(size_t)S_ * HID_];                // single fp16 hidden
__device__ __half g_wqkvt[(size_t)QKVN_ * HID_];          // (Wq|Wk|Wv)^T single fp16
__device__ __half g_wot[(size_t)HID_ * HID_];             // Wo^T single fp16
__device__ __half g_qhat[(size_t)NH_ * S_ * D_];          // single fp16 roped Q
__device__ __half g_khat[(size_t)NKV_ * S_ * D_];         // single fp16 roped K
__device__ __half g_vthat[(size_t)NKV_ * D_ * S_];        // single fp16 V^T
__device__ __half g_aohat[(size_t)S_ * HID_];             // single fp16 attention out

// ----------------------------- PTX helpers ------------------------------
__device__ __forceinline__ uint32_t smem_u32(const void* p) {
    uint32_t a;
    asm("{ .reg .u64 t; cvta.to.shared.u64 t, %1; cvt.u32.u64 %0, t; }" : "=r"(a) : "l"(p));
    return a;
}
__device__ __forceinline__ void cp16(uint32_t saddr, const void* gptr) {
    asm volatile("cp.async.cg.shared.global [%0], [%1], 16;" :: "r"(saddr), "l"(gptr));
}
__device__ __forceinline__ void cp_commit() { asm volatile("cp.async.commit_group;"); }
__device__ __forceinline__ void cp_wait0() { asm volatile("cp.async.wait_group 0;" ::: "memory"); }
__device__ __forceinline__ void cp_wait1() { asm volatile("cp.async.wait_group 1;" ::: "memory"); }

__device__ __forceinline__ void ldsm4(uint32_t& r0, uint32_t& r1, uint32_t& r2, uint32_t& r3,
                                      uint32_t addr) {
    asm volatile("ldmatrix.sync.aligned.m8n8.x4.shared.b16 {%0,%1,%2,%3}, [%4];"
                 : "=r"(r0), "=r"(r1), "=r"(r2), "=r"(r3) : "r"(addr));
}
__device__ __forceinline__ void mma16816(float* d, const uint32_t* a, const uint32_t* b) {
    asm volatile(
        "mma.sync.aligned.m16n8k16.row.col.f32.f16.f16.f32 "
        "{%0,%1,%2,%3}, {%4,%5,%6,%7}, {%8,%9}, {%0,%1,%2,%3};"
        : "+f"(d[0]), "+f"(d[1]), "+f"(d[2]), "+f"(d[3])
        : "r"(a[0]), "r"(a[1]), "r"(a[2]), "r"(a[3]), "r"(b[0]), "r"(b[1]));
}
__device__ __forceinline__ float fexp(float x) {   // e^x via MUFU
    float y;
    asm("ex2.approx.ftz.f32 %0, %1;" : "=f"(y) : "f"(x * L2E_));
    return y;
}
__device__ __forceinline__ float fexp2p3(float x) { // 2^x via FMA pipe, deg-3
    float n = rintf(x);
    float f = x - n;
    float p = 5.5490603e-2f;
    p = fmaf(p, f, 2.4022651e-1f);
    p = fmaf(p, f, 6.9315308e-1f);
    p = fmaf(p, f, 9.9999989e-1f);
    return p * __int_as_float(((int)n + 127) << 23);
}
__device__ __forceinline__ uint32_t packh(float p0, float p1) {
    __half2 h = __floats2half2_rn(p0, p1);
    return *(uint32_t*)&h;
}

// ------------------------- HMMA GEMM -------------------------
__device__ __forceinline__ void load_tile_async(uint32_t sbase, const __half* src,
                                                int ld, int row0, int kbase, int tid) {
#pragma unroll
    for (int t = 0; t < 4; t++) {
        int u = tid + t * 256;
        int row = u >> 3, seg = u & 7;
        uint32_t bo = (uint32_t)(row * 128 + seg * 16);
        bo ^= (bo >> 3) & 0x70;
        cp16(sbase + bo, src + (size_t)(row0 + row) * ld + kbase + seg * 8);
    }
}

// mode 0: plain fp32 store to C.
// mode 2: Eh = fp16(exp(scale*s)) for j<=i (0 above), hybrid exp, fused row sums.
__global__ __launch_bounds__(256, 2) void mma_gemm(
    const __half* __restrict__ A, size_t aStrideZ, int aLd,
    const __half* __restrict__ Bt, size_t bStrideZ, int bShift, int bLd,
    float* __restrict__ C, __half* __restrict__ Eh, size_t cStrideZ, int ldc,
    int Kp, int mode, float* __restrict__ rowsum) {
    int z = blockIdx.z;
    int i0 = blockIdx.y * 128, j0 = blockIdx.x * 128;
    if (mode == 2 && j0 > i0 + 127) return;

    const __half* Az = A + (size_t)z * aStrideZ;
    const __half* Bz = Bt + (size_t)(z >> bShift) * bStrideZ;
    int tid = threadIdx.x, wid = tid >> 5;
    uint32_t lane = tid & 31;

    extern __shared__ char dsm[];
    char* tile = (char*)(((uintptr_t)dsm + 1023) & ~(uintptr_t)1023);
    uint32_t sA[2] = { smem_u32(tile), smem_u32(tile) + 16384 };
    uint32_t sB[2] = { smem_u32(tile) + 32768, smem_u32(tile) + 49152 };

    int warp_m = wid >> 2;
    int warp_n = wid & 3;

    float acc[4][4][4];
#pragma unroll
    for (int i = 0; i < 4; i++)
#pragma unroll
        for (int j = 0; j < 4; j++)
#pragma unroll
            for (int r = 0; r < 4; r++) acc[i][j][r] = 0.f;

    load_tile_async(sA[0], Az, aLd, i0, 0, tid);
    load_tile_async(sB[0], Bz, bLd, j0, 0, tid);
    cp_commit();

    const int NC = Kp >> 6;
    for (int c = 0; c < NC; c++) {
        if (c + 1 < NC) {
            load_tile_async(sA[(c + 1) & 1], Az, aLd, i0, (c + 1) * 64, tid);
            load_tile_async(sB[(c + 1) & 1], Bz, bLd, j0, (c + 1) * 64, tid);
            cp_commit();
            cp_wait1();
        } else {
            cp_wait0();
        }
        __syncthreads();

        uint32_t a_base = sA[c & 1], b_base = sB[c & 1];
#pragma unroll
        for (int ks = 0; ks < 4; ks++) {
            uint32_t a[4][4], b[2][4];
#pragma unroll
            for (int mf = 0; mf < 4; mf++) {
                int row = 64 * warp_m + 16 * mf + (lane & 7) + (((lane >> 3) & 1) << 3);
                int colb = (16 * ks + (((lane >> 4) & 1) << 3)) * 2;
                uint32_t off = (uint32_t)(row * 128 + colb);
                off ^= (off >> 3) & 0x70;
                ldsm4(a[mf][0], a[mf][1], a[mf][2], a[mf][3], a_base + off);
            }
#pragma unroll
            for (int nf2 = 0; nf2 < 2; nf2++) {
                int row = 32 * warp_n + 16 * nf2 + (lane & 7) + (((lane >> 4) & 1) << 3);
                int colb = (16 * ks + (((lane >> 3) & 1) << 3)) * 2;
                uint32_t off = (uint32_t)(row * 128 + colb);
                off ^= (off >> 3) & 0x70;
                ldsm4(b[nf2][0], b[nf2][1], b[nf2][2], b[nf2][3], b_base + off);
            }
#pragma unroll
            for (int mf = 0; mf < 4; mf++)
#pragma unroll
                for (int nf = 0; nf < 4; nf++)
                    mma16816(acc[mf][nf], a[mf], &b[nf >> 1][(nf & 1) * 2]);
        }
        __syncthreads();
    }

    if (mode == 0) {
        float* Cz = C + (size_t)z * cStrideZ;
#pragma unroll
        for (int mf = 0; mf < 4; mf++) {
            int r0 = i0 + 64 * warp_m + 16 * mf + (int)(lane >> 2);
#pragma unroll
            for (int nf = 0; nf < 4; nf++) {
                int c0 = j0 + 32 * warp_n + 8 * nf + (int)(lane & 3) * 2;
                *(float2*)(Cz + (size_t)r0 * ldc + c0) = make_float2(acc[mf][nf][0], acc[mf][nf][1]);
                *(float2*)(Cz + (size_t)(r0 + 8) * ldc + c0) = make_float2(acc[mf][nf][2], acc[mf][nf][3]);
            }
        }
        return;
    }

    // mode 2: exp epilogue (10/16 MUFU + 6/16 deg-3 poly), fp16 store, fused row sums
    __half* Ez = Eh + (size_t)z * cStrideZ;
    const float cl = SCALE_ * L2E_;
    float rs0[4], rs1[4];
#pragma unroll
    for (int mf = 0; mf < 4; mf++) {
        int r0 = i0 + 64 * warp_m + 16 * mf + (int)(lane >> 2);
        float s0 = 0.f, s1 = 0.f;
#pragma unroll
        for (int nf = 0; nf < 4; nf++) {
            int c0 = j0 + 32 * warp_n + 8 * nf + (int)(lane & 3) * 2;
            float d0 = acc[mf][nf][0], d1 = acc[mf][nf][1];
            float d2 = acc[mf][nf][2], d3 = acc[mf][nf][3];
            if (nf < 2) {
                d0 = (c0     <= r0)     ? fexp(d0 * SCALE_) : 0.f;
                d1 = (c0 + 1 <= r0)     ? fexp(d1 * SCALE_) : 0.f;
                d2 = (c0     <= r0 + 8) ? fexp(d2 * SCALE_) : 0.f;
                d3 = (c0 + 1 <= r0 + 8) ? fexp(d3 * SCALE_) : 0.f;
            } else if (nf == 2) {
                d0 = (c0     <= r0)     ? fexp(d0 * SCALE_) : 0.f;
                d1 = (c0 + 1 <= r0)     ? fexp(d1 * SCALE_) : 0.f;
                d2 = (c0     <= r0 + 8) ? fexp2p3(d2 * cl) : 0.f;
                d3 = (c0 + 1 <= r0 + 8) ? fexp2p3(d3 * cl) : 0.f;
            } else {
                d0 = (c0     <= r0)     ? fexp2p3(d0 * cl) : 0.f;
                d1 = (c0 + 1 <= r0)     ? fexp2p3(d1 * cl) : 0.f;
                d2 = (c0     <= r0 + 8) ? fexp2p3(d2 * cl) : 0.f;
                d3 = (c0 + 1 <= r0 + 8) ? fexp2p3(d3 * cl) : 0.f;
            }
            __half2 h01 = __floats2half2_rn(d0, d1);
            __half2 h23 = __floats2half2_rn(d2, d3);
            *(uint32_t*)(Ez + (size_t)r0 * ldc + c0) = *(uint32_t*)&h01;
            *(uint32_t*)(Ez + (size_t)(r0 + 8) * ldc + c0) = *(uint32_t*)&h23;
            float2 f01 = __half22float2(h01);
            float2 f23 = __half22float2(h23);
            s0 += f01.x + f01.y;
            s1 += f23.x + f23.y;
        }
        rs0[mf] = s0; rs1[mf] = s1;
    }
    {
        float* rz = rowsum + (size_t)z * S_;
#pragma unroll
        for (int mf = 0; mf < 4; mf++) {
            float v0 = rs0[mf], v1 = rs1[mf];
            v0 += __shfl_xor_sync(0xFFFFFFFF, v0, 1);
            v0 += __shfl_xor_sync(0xFFFFFFFF, v0, 2);
            v1 += __shfl_xor_sync(0xFFFFFFFF, v1, 1);
            v1 += __shfl_xor_sync(0xFFFFFFFF, v1, 2);
            if ((lane & 3) == 0) {
                int r0 = i0 + 64 * warp_m + 16 * mf + (int)(lane >> 2);
                atomicAdd(rz + r0, v0);
                atomicAdd(rz + r0 + 8, v1);
            }
        }
    }
}

// ------------------ fused PV (masked P on the fly, single-pass fp16) --------------
__global__ __launch_bounds__(256, 2) void pv_mma(
    const __half* __restrict__ vthat,
    const __half* __restrict__ e, const float* __restrict__ invl2,
    const uint32_t* __restrict__ heavybits,
    __half* __restrict__ aohat) {
    int i0 = (int)(gridDim.x - 1 - blockIdx.x) * 128;   // heavy blocks first
    int h = blockIdx.y, kh = h >> 2;
    int tid = threadIdx.x, wid = tid >> 5;
    uint32_t lane = tid & 31;
    int warp_m = wid >> 2, warp_n = wid & 3;

    extern __shared__ char dsm[];
    char* tile = (char*)(((uintptr_t)dsm + 1023) & ~(uintptr_t)1023);
    char* pP = tile;
    uint32_t sP = smem_u32(pP);
    uint32_t sV[2] = { smem_u32(tile) + 16384, smem_u32(tile) + 32768 };

    __shared__ uint32_t sbits[64];
    if (tid < 64) sbits[tid] = heavybits[h * 64 + tid];

    int r = tid >> 1, half = tid & 1;
    int gi = i0 + r;
    float il = invl2[h * S_ + gi];
    const __half* erow = e + ((size_t)h * S_ + gi) * S_ + half * 32;
    const __half* Vz = vthat + (size_t)kh * D_ * S_;

    float acc[4][4][4];
#pragma unroll
    for (int i = 0; i < 4; i++)
#pragma unroll
        for (int j = 0; j < 4; j++)
#pragma unroll
            for (int q = 0; q < 4; q++) acc[i][j][q] = 0.f;

    const int NCH = (i0 >> 6) + 2;
    load_tile_async(sV[0], Vz, S_, 0, 0, tid);
    cp_commit();
    __syncthreads();

    for (int c = 0; c < NCH; c++) {
        int j0 = c * 64;
        bool pre = (c + 1 < NCH);
        if (pre) {
            load_tile_async(sV[(c + 1) & 1], Vz, S_, 0, (c + 1) * 64, tid);
            cp_commit();
        }
        uint32_t hib[16];
        const __half* ep = erow + j0;
        int gjb = j0 + half * 32;
#pragma unroll
        for (int w = 0; w < 4; w++) {
            uint4 ev = *(const uint4*)(ep + w * 8);
            float2 f0 = __half22float2(*(__half2*)&ev.x);
            float2 f1 = __half22float2(*(__half2*)&ev.y);
            float2 f2 = __half22float2(*(__half2*)&ev.z);
            float2 f3 = __half22float2(*(__half2*)&ev.w);
            float pv[8] = { f0.x, f0.y, f1.x, f1.y, f2.x, f2.y, f3.x, f3.y };
#pragma unroll
            for (int u = 0; u < 8; u++) {
                int gj = gjb + w * 8 + u;
                bool keep = (gj <= gi) &&
                            ((gi - gj <= RB_) || ((sbits[gj >> 5] >> (gj & 31)) & 1u));
                pv[u] = keep ? pv[u] * il : 0.f;
            }
            hib[w * 4 + 0] = packh(pv[0], pv[1]);
            hib[w * 4 + 1] = packh(pv[2], pv[3]);
            hib[w * 4 + 2] = packh(pv[4], pv[5]);
            hib[w * 4 + 3] = packh(pv[6], pv[7]);
        }
#pragma unroll
        for (int sg = 0; sg < 4; sg++) {
            uint32_t bo = (uint32_t)(r * 128 + half * 64 + sg * 16);
            bo ^= (bo >> 3) & 0x70;
            *(uint4*)(pP + bo) = make_uint4(hib[sg * 4], hib[sg * 4 + 1], hib[sg * 4 + 2], hib[sg * 4 + 3]);
        }
        if (pre) cp_wait1(); else cp_wait0();
        __syncthreads();

        uint32_t b_base = sV[c & 1];
#pragma unroll
        for (int ks = 0; ks < 4; ks++) {
            uint32_t a[4][4], b[2][4];
#pragma unroll
            for (int mf = 0; mf < 4; mf++) {
                int row = 64 * warp_m + 16 * mf + (lane & 7) + (((lane >> 3) & 1) << 3);
                int colb = (16 * ks + (((lane >> 4) & 1) << 3)) * 2;
                uint32_t off = (uint32_t)(row * 128 + colb);
                off ^= (off >> 3) & 0x70;
                ldsm4(a[mf][0], a[mf][1], a[mf][2], a[mf][3], sP + off);
            }
#pragma unroll
            for (int nf2 = 0; nf2 < 2; nf2++) {
                int row = 32 * warp_n + 16 * nf2 + (lane & 7) + (((lane >> 4) & 1) << 3);
                int colb = (16 * ks + (((lane >> 3) & 1) << 3)) * 2;
                uint32_t off = (uint32_t)(row * 128 + colb);
                off ^= (off >> 3) & 0x70;
                ldsm4(b[nf2][0], b[nf2][1], b[nf2][2], b[nf2][3], b_base + off);
            }
#pragma unroll
            for (int mf = 0; mf < 4; mf++)
#pragma unroll
                for (int nf = 0; nf < 4; nf++)
                    mma16816(acc[mf][nf], a[mf], &b[nf >> 1][(nf & 1) * 2]);
        }
        __syncthreads();
    }

#pragma unroll
    for (int mf = 0; mf < 4; mf++) {
        int r0 = i0 + 64 * warp_m + 16 * mf + (int)(lane >> 2);
#pragma unroll
        for (int nf = 0; nf < 4; nf++) {
            int c0 = 32 * warp_n + 8 * nf + (int)(lane & 3) * 2;
#pragma unroll
            for (int rr = 0; rr < 2; rr++) {
                uint32_t hi = packh(acc[mf][nf][rr * 2], acc[mf][nf][rr * 2 + 1]);
                size_t b0 = (size_t)(r0 + rr * 8) * HID_ + h * D_ + c0;
                *(uint32_t*)(aohat + b0) = hi;
            }
        }
    }
}

// ----------------------- conversion kernels -------------------
__global__ void tofp16_kernel(const float* __restrict__ A, __half* __restrict__ out, int n) {
    int idx = blockIdx.x * blockDim.x + threadIdx.x;
    if (idx < n) out[idx] = __float2half_rn(A[idx]);
}

// fused RoPE + fp16 conversion to per-head layout out[h][s][d]
__global__ void rope_heads(const float* __restrict__ src, int ld,
                           __half* __restrict__ out, int nh) {
    int idx = blockIdx.x * blockDim.x + threadIdx.x;
    if (idx >= S_ * nh * 64) return;
    int d = idx & 63;
    int rest = idx >> 6;
    int h = rest % nh;
    int s = rest / nh;
    const float* base = src + (size_t)s * ld + h * 128;
    float x1 = base[d], x2 = base[d + 64];
    float inv = powf(10000.f, -(float)d * (1.f / 64.f));
    float ang = (float)s * inv;
    float c, sn;
    sincosf(ang, &sn, &c);
    __half* ob = out + ((size_t)h * S_ + s) * D_;
    ob[d]      = __float2half_rn(x1 * c - x2 * sn);
    ob[d + 64] = __float2half_rn(x2 * c + x1 * sn);
}

__global__ void transpose_half(const float* __restrict__ src, int ldsrc, int K, int Nper,
                               __half* __restrict__ out) {
    int z = blockIdx.z;
    const float* s = src + (size_t)z * Nper;
    __half* o = out + (size_t)z * Nper * K;
    __shared__ float t[32][33];
    int k0 = blockIdx.y * 32, n0 = blockIdx.x * 32;
    int tx = threadIdx.x, ty = threadIdx.y;
#pragma unroll
    for (int r = 0; r < 4; r++) {
        int k = k0 + ty + 8 * r;
        t[ty + 8 * r][tx] = s[(size_t)k * ldsrc + n0 + tx];
    }
    __syncthreads();
#pragma unroll
    for (int r = 0; r < 4; r++) {
        int n = n0 + ty + 8 * r, k = k0 + tx;
        o[(size_t)n * K + k] = __float2half_rn(t[tx][ty + 8 * r]);
    }
}

// ------------------ invl1 = 1 / rowsum -----------------------------------
__global__ void invl_kernel(const float* __restrict__ rs, float* __restrict__ il) {
    int i = blockIdx.x * 256 + threadIdx.x;
    il[i] = 1.f / rs[i];
}

// coalesced column sums over fp16 e (rows above diagonal are exactly zero)
__global__ __launch_bounds__(256) void colsum_kernel() {
    int h = blockIdx.y;
    int j0 = blockIdx.x * 256;
    int j = j0 + threadIdx.x;
    const __half* base = g_e + (size_t)h * S_ * S_;
    __shared__ float il[S_];
    for (int i = j0 + threadIdx.x; i < S_; i += 256)
        il[i] = g_invl1[h * S_ + i];
    __syncthreads();
    float a0 = 0.f, a1 = 0.f, a2 = 0.f, a3 = 0.f;
    for (int i = j0; i < S_; i += 4) {
        a0 += __half2float(base[(size_t)(i    ) * S_ + j]) * il[i];
        a1 += __half2float(base[(size_t)(i + 1) * S_ + j]) * il[i + 1];
        a2 += __half2float(base[(size_t)(i + 2) * S_ + j]) * il[i + 2];
        a3 += __half2float(base[(size_t)(i + 3) * S_ + j]) * il[i + 3];
    }
    g_colsum[h * S_ + j] = (a0 + a1) + (a2 + a3);
}

__global__ __launch_bounds__(256) void topk_kernel() {
    int h = blockIdx.x;
    int tid = threadIdx.x;
    int lane = tid & 31, w = tid >> 5;
    __shared__ float vals[S_];
    __shared__ float wbv[8];
    __shared__ int wbi[8];
    __shared__ uint32_t bits[64];
    for (int j = tid; j < S_; j += 256) vals[j] = g_colsum[h * S_ + j];
    if (tid < 64) bits[tid] = 0;
    __syncthreads();
    for (int it = 0; it < HB_; it++) {
        float best = -INFINITY; int besti = 1 << 30;
        for (int j = tid; j < S_; j += 256) {
            float v = vals[j];
            if (v > best || (v == best && j < besti)) { best = v; besti = j; }
        }
#pragma unroll
        for (int off = 16; off > 0; off >>= 1) {
            float ov = __shfl_xor_sync(0xFFFFFFFF, best, off);
            int oi = __shfl_xor_sync(0xFFFFFFFF, besti, off);
            if (ov > best || (ov == best && oi < besti)) { best = ov; besti = oi; }
        }
        if (lane == 0) { wbv[w] = best; wbi[w] = besti; }
        __syncthreads();
        if (tid == 0) {
            float b = wbv[0]; int bi2 = wbi[0];
#pragma unroll
            for (int q = 1; q < 8; q++)
                if (wbv[q] > b || (wbv[q] == b && wbi[q] < bi2)) { b = wbv[q]; bi2 = wbi[q]; }
            g_heavylist[h * HB_ + it] = bi2;
            bits[bi2 >> 5] |= (1u << (bi2 & 31));
            vals[bi2] = -INFINITY;
        }
        __syncthreads();
    }
    if (tid < 64) g_heavybits[h * 64 + tid] = bits[tid];
}

// ------ pass-2: invl2 = 1/sum(e over band + heavy) ------
__global__ __launch_bounds__(256) void rowsum2_kernel() {
    int h = blockIdx.y;
    int tid = threadIdx.x;
    __shared__ int hl[HB_];
    for (int t = tid; t < HB_; t += 256) hl[t] = g_heavylist[h * HB_ + t];
    __syncthreads();

    int w = tid >> 5, lane = tid & 31;
    int i = blockIdx.x * 8 + w;
    const __half* erow = g_e + (size_t)(h * S_ + i) * S_;
    int lo = i - RB_; if (lo < 0) lo = 0;

    float l = 0.f;
    for (int j = lo + lane; j <= i; j += 32) l += __half2float(erow[j]);
    for (int t = lane; t < HB_; t += 32) {
        int j = hl[t];
        if (j < lo) l += __half2float(erow[j]);
    }
#pragma unroll
    for (int off = 16; off > 0; off >>= 1)
        l += __shfl_xor_sync(0xFFFFFFFF, l, off);
    if (lane == 0) g_invl2[h * S_ + i] = 1.f / l;
}

// ------------------------------ launcher ---------------------------------
extern "C" void kernel_launch(void* const* d_in, const int* in_sizes, int n_in,
                              void* d_out, int out_size) {
    const float* hidden = (const float*)d_in[0];
    const float* Wq = (const float*)d_in[1];
    const float* Wk = (const float*)d_in[2];
    const float* Wv = (const float*)d_in[3];
    const float* Wo = (const float*)d_in[4];
    float* out = (float*)d_out;

    float *qkv, *rsum, *il1, *il2;
    __half* e;
    uint32_t* hbits;
    __half *xh, *wqkvt, *wot, *qhat, *khat, *vthat, *aohat;
    cudaGetSymbolAddress((void**)&qkv, g_qkv);
    cudaGetSymbolAddress((void**)&e, g_e);
    cudaGetSymbolAddress((void**)&rsum, g_rowsum);
    cudaGetSymbolAddress((void**)&il1, g_invl1);
    cudaGetSymbolAddress((void**)&il2, g_invl2);
    cudaGetSymbolAddress((void**)&hbits, g_heavybits);
    cudaGetSymbolAddress((void**)&xh, g_xh);
    cudaGetSymbolAddress((void**)&wqkvt, g_wqkvt);
    cudaGetSymbolAddress((void**)&wot, g_wot);
    cudaGetSymbolAddress((void**)&qhat, g_qhat);
    cudaGetSymbolAddress((void**)&khat, g_khat);
    cudaGetSymbolAddress((void**)&vthat, g_vthat);
    cudaGetSymbolAddress((void**)&aohat, g_aohat);

    const int SMEM_GEMM = 66560;
    const int SMEM_PV = 50176;
    cudaFuncSetAttribute(mma_gemm, cudaFuncAttributeMaxDynamicSharedMemorySize, SMEM_GEMM);
    cudaFuncSetAttribute(pv_mma, cudaFuncAttributeMaxDynamicSharedMemorySize, SMEM_PV);

    // conversions (QKV mma is launch #6 -> ncu -s 5 capture)
    tofp16_kernel<<<(S_ * HID_ + 255) / 256, 256>>>(hidden, xh, S_ * HID_);
    transpose_half<<<dim3(HID_ / 32, HID_ / 32, 1), dim3(32, 8)>>>(Wq, HID_, HID_, HID_, wqkvt);
    transpose_half<<<dim3((NKV_ * D_) / 32, HID_ / 32, 1), dim3(32, 8)>>>(
        Wk, NKV_ * D_, HID_, NKV_ * D_, wqkvt + (size_t)HID_ * HID_);
    transpose_half<<<dim3((NKV_ * D_) / 32, HID_ / 32, 1), dim3(32, 8)>>>(
        Wv, NKV_ * D_, HID_, NKV_ * D_, wqkvt + (size_t)(HID_ + NKV_ * D_) * HID_);
    transpose_half<<<dim3(HID_ / 32, HID_ / 32, 1), dim3(32, 8)>>>(Wo, HID_, HID_, HID_, wot);

    // 6. fused QKV projection (single fp16, 128-tile kernel: 2048x3072x2048)
    mma_gemm<<<dim3(QKVN_ / 128, S_ / 128, 1), 256, SMEM_GEMM>>>(
        xh, 0, HID_, wqkvt, 0, 0, HID_,
        qkv, nullptr, 0, QKVN_, HID_, 0, nullptr);

    // fused RoPE + fp16 per-head conversion; V -> single fp16 V^T
    rope_heads<<<(S_ * NH_ * 64 + 255) / 256, 256>>>(qkv, QKVN_, qhat, NH_);
    rope_heads<<<(S_ * NKV_ * 64 + 255) / 256, 256>>>(qkv + HID_, QKVN_, khat, NKV_);
    transpose_half<<<dim3(D_ / 32, S_ / 32, NKV_), dim3(32, 8)>>>(
        qkv + HID_ + NKV_ * D_, QKVN_, S_, D_, vthat);

    // zero rowsum accumulator
    cudaMemsetAsync(rsum, 0, NH_ * S_ * sizeof(float));

    // e = fp16(exp(scale * QK^T)), single fp16 both sides, Kp = D
    mma_gemm<<<dim3(S_ / 128, S_ / 128, NH_), 256, SMEM_GEMM>>>(
        qhat, (size_t)S_ * D_, D_, khat, (size_t)S_ * D_, 2, D_,
        nullptr, e, (size_t)S_ * S_, S_, D_, 2, rsum);

    // H2O: invl1, colsum, topk
    invl_kernel<<<NH_ * S_ / 256, 256>>>(rsum, il1);
    colsum_kernel<<<dim3(S_ / 256, NH_), 256>>>();
    topk_kernel<<<NH_, 256>>>();

    // invl2
    rowsum2_kernel<<<dim3(S_ / 8, NH_), 256>>>();

    // fused masked PV -> aohat (single fp16)
    pv_mma<<<dim3(S_ / 128, NH_), 256, SMEM_PV>>>(vthat, e, il2, hbits, aohat);

    // output projection (single fp16 both sides, Kp = HID)
    mma_gemm<<<dim3(HID_ / 128, S_ / 128, 1), 256, SMEM_GEMM>>>(
        aohat, 0, HID_, wot, 0, 0, HID_,
        out, nullptr, 0, HID_, HID_, 0, nullptr);
}